// round 1
// baseline (speedup 1.0000x reference)
#include <cuda_runtime.h>
#include <math.h>

// Problem constants (fixed shapes for this problem instance)
#define BB 8
#define SS 4096
#define HH 1152
#define LL 256
#define HV (HH / 4)   // 288 float4 lanes per row

// Scratch: packed (kidx | pad<<16) per token. 8*4096*4 = 128 KB, L2-resident.
__device__ int g_kidx[BB * SS];

// ---------------------------------------------------------------------------
// Kernel A: per-batch max_x reduction + kernel-index computation
// ---------------------------------------------------------------------------
__global__ void kidx_kernel(const int* __restrict__ ppi,
                            const unsigned char* __restrict__ pad,
                            int k) {
    const int b = blockIdx.x;
    const int t = threadIdx.x;
    __shared__ int smax[256];

    int mx = 0;
    for (int s = t; s < SS; s += 256) {
        int x = ppi[((long long)b * SS + s) * 2 + 0];
        if (x < 0) x = 0;
        mx = max(mx, x);
    }
    smax[t] = mx;
    __syncthreads();
    #pragma unroll
    for (int off = 128; off > 0; off >>= 1) {
        if (t < off) smax[t] = max(smax[t], smax[t + off]);
        __syncthreads();
    }
    const int factor = (smax[0] + 1) / k;   // (max_x) // k with max_x = max+1

    for (int s = t; s < SS; s += 256) {
        const long long base = (long long)b * SS + s;
        int x = ppi[base * 2 + 0];
        int y = ppi[base * 2 + 1];
        if (x < 0) x = 0;
        if (y < 0) y = 0;
        int kidx = x / k + factor * (y / k);
        // clamp to 16-bit field; anything >= LL simply never matches a block
        if (kidx > 0xFFFF || kidx < 0) kidx = 0xFFFF;
        g_kidx[base] = kidx | (pad[base] ? 0x10000 : 0);
    }
}

// ---------------------------------------------------------------------------
// Kernel B: one block per (l, b). Build match list, then coalesced row sum.
// ---------------------------------------------------------------------------
__global__ __launch_bounds__(HV) void pool_kernel(
    const float4* __restrict__ hs,
    float4* __restrict__ out,
    float* __restrict__ mask,
    float scale) {
    const int l = blockIdx.x;
    const int b = blockIdx.y;
    const int t = threadIdx.x;

    __shared__ int s_list[SS];
    __shared__ int s_count;
    if (t == 0) s_count = 0;
    __syncthreads();

    const int* kb = g_kidx + b * SS;
    for (int s = t; s < SS; s += HV) {
        const int v = kb[s];
        if ((v & 0xFFFF) == l) {
            const int pos = atomicAdd(&s_count, 1);
            s_list[pos] = s | ((v & 0x10000) ? 0x40000000 : 0); // bit30 = padded
        }
    }
    __syncthreads();
    const int cnt = s_count;

    // Determinism: sort small lists so FP summation order is fixed.
    if (t == 0 && cnt > 1 && cnt <= 64) {
        for (int i = 1; i < cnt; i++) {
            const int v = s_list[i];
            const int key = v & 0x3FFFFFFF;
            int j = i - 1;
            while (j >= 0 && (s_list[j] & 0x3FFFFFFF) > key) {
                s_list[j + 1] = s_list[j];
                j--;
            }
            s_list[j + 1] = v;
        }
    }
    __syncthreads();

    float4 acc = make_float4(0.f, 0.f, 0.f, 0.f);
    for (int i = 0; i < cnt; i++) {
        const int v = s_list[i];
        if (v & 0x40000000) continue;  // padded row contributes zero
        const float4 x = __ldg(hs + ((long long)b * SS + v) * HV + t);
        acc.x += x.x; acc.y += x.y; acc.z += x.z; acc.w += x.w;
    }
    acc.x *= scale; acc.y *= scale; acc.z *= scale; acc.w *= scale;
    out[((long long)b * LL + l) * HV + t] = acc;

    if (t == 0 && mask != nullptr)
        mask[(long long)b * LL + l] = (cnt > 0) ? 1.0f : 0.0f;
}

// ---------------------------------------------------------------------------
// Launch
// ---------------------------------------------------------------------------
extern "C" void kernel_launch(void* const* d_in, const int* in_sizes, int n_in,
                              void* d_out, int out_size) {
    const float*         hs  = (const float*)d_in[0];          // [B,S,H] f32
    const int*           ppi = (const int*)d_in[1];            // [B,S,2] i32
    const unsigned char* pad = (const unsigned char*)d_in[2];  // [B,S] bool

    const int k = 4;                       // sqrt(S / output_length)
    const float scale = sqrtf((float)HH) / (float)(k * k);

    kidx_kernel<<<BB, 256>>>(ppi, pad, k);

    float* out  = (float*)d_out;
    float* mask = nullptr;
    const long long pooled_elems = (long long)BB * LL * HH;
    if ((long long)out_size >= pooled_elems + (long long)BB * LL)
        mask = out + pooled_elems;

    pool_kernel<<<dim3(LL, BB), HV>>>((const float4*)hs, (float4*)out, mask, scale);
}

// round 2
// speedup vs baseline: 1.1675x; 1.1675x over previous
#include <cuda_runtime.h>
#include <math.h>

// Fixed problem shapes
#define BB 8
#define SS 4096
#define HH 1152
#define LL 256
#define HV (HH / 4)    // 288 float4 lanes per row
#define KK 4           // pool factor: sqrt(S / output_length)
#define NWARP 9        // 288 / 32
#define CHUNK ((SS + NWARP - 1) / NWARP)   // 456 tokens per warp

// Scratch (L2-resident)
__device__ int g_factor[BB];       // (max_x + 1) / KK per batch
__device__ int g_kidx[BB * SS];    // packed: kidx | (pad << 16)

// ---------------------------------------------------------------------------
// Kernel 1: per-batch max_x -> factor. 8 loads in flight per thread (MLP=8).
// ---------------------------------------------------------------------------
__global__ __launch_bounds__(512) void maxx_kernel(const int2* __restrict__ ppi) {
    const int b = blockIdx.x;
    const int t = threadIdx.x;
    __shared__ int smax[16];

    const int2* p = ppi + (long long)b * SS;
    int2 v[8];
    #pragma unroll
    for (int i = 0; i < 8; i++) v[i] = p[t + i * 512];
    int mx = 0;
    #pragma unroll
    for (int i = 0; i < 8; i++) mx = max(mx, v[i].x);

    #pragma unroll
    for (int off = 16; off > 0; off >>= 1)
        mx = max(mx, __shfl_xor_sync(0xFFFFFFFFu, mx, off));
    if ((t & 31) == 0) smax[t >> 5] = mx;
    __syncthreads();
    if (t == 0) {
        int m = smax[0];
        #pragma unroll
        for (int i = 1; i < 16; i++) m = max(m, smax[i]);
        if (m < 0) m = 0;
        g_factor[b] = (m + 1) / KK;
    }
}

// ---------------------------------------------------------------------------
// Kernel 2: compute packed kidx for all tokens. 64 blocks x 256 thr.
// ---------------------------------------------------------------------------
__global__ __launch_bounds__(256) void kidx_kernel(
    const int2* __restrict__ ppi,
    const unsigned char* __restrict__ pad) {
    const int b = blockIdx.y;
    const int factor = g_factor[b];
    const int s0 = blockIdx.x * 512 + threadIdx.x;

    #pragma unroll
    for (int r = 0; r < 2; r++) {
        const int s = s0 + r * 256;
        const long long base = (long long)b * SS + s;
        int2 p = ppi[base];
        int x = max(p.x, 0);
        int y = max(p.y, 0);
        long long kidx = (long long)(x / KK) + (long long)factor * (y / KK);
        int ki = (kidx > 0xFFFF || kidx < 0) ? 0xFFFF : (int)kidx;
        g_kidx[base] = ki | (pad[base] ? 0x10000 : 0);
    }
}

// ---------------------------------------------------------------------------
// Kernel 3: one block per (l,b). Warp-ballot ordered list build, then
// 4-way-unrolled coalesced row accumulation.
// ---------------------------------------------------------------------------
__global__ __launch_bounds__(HV) void pool_kernel(
    const float4* __restrict__ hs,
    float4* __restrict__ out,
    float* __restrict__ mask,
    float scale) {
    const int l = blockIdx.x;
    const int b = blockIdx.y;
    const int t = threadIdx.x;
    const int w = t >> 5;
    const int lane = t & 31;
    const unsigned lt = (1u << lane) - 1u;

    __shared__ int s_list[SS];
    __shared__ int s_wcnt[NWARP];   // non-pad matches per warp chunk
    __shared__ int s_off[NWARP];    // exclusive scan
    __shared__ int s_cnt, s_total;

    const int* kb = g_kidx + b * SS;
    const int begin = w * CHUNK;
    const int end = min(begin + CHUNK, SS);

    // Pass 1: count matches (total incl. pad for the mask; non-pad for the list)
    int c_np = 0, c_tot = 0;
    for (int sb = begin; sb < end; sb += 32) {
        const int s = sb + lane;
        const int v = (s < end) ? kb[s] : -1;
        const bool m = ((v & 0xFFFF) == l);
        const unsigned bt = __ballot_sync(0xFFFFFFFFu, m);
        const unsigned bn = __ballot_sync(0xFFFFFFFFu, m && !(v & 0x10000));
        c_tot += __popc(bt);
        c_np += __popc(bn);
    }
    if (lane == 0) s_wcnt[w] = c_np;
    // accumulate total matches via warp-0-lane reduction per warp, then shared
    __shared__ int s_tot_w[NWARP];
    if (lane == 0) s_tot_w[w] = c_tot;
    __syncthreads();
    if (t == 0) {
        int acc = 0, tot = 0;
        #pragma unroll
        for (int i = 0; i < NWARP; i++) {
            s_off[i] = acc;
            acc += s_wcnt[i];
            tot += s_tot_w[i];
        }
        s_cnt = acc;
        s_total = tot;
    }
    __syncthreads();

    // Pass 2: ordered compaction (sorted by s, deterministic)
    int off = s_off[w];
    for (int sb = begin; sb < end; sb += 32) {
        const int s = sb + lane;
        const int v = (s < end) ? kb[s] : -1;
        const bool m = ((v & 0xFFFF) == l) && !(v & 0x10000);
        const unsigned bn = __ballot_sync(0xFFFFFFFFu, m);
        if (m) s_list[off + __popc(bn & lt)] = s;
        off += __popc(bn);
    }
    __syncthreads();
    const int cnt = s_cnt;

    // Accumulate rows: 4-way unroll, 4 independent accumulators (MLP=4)
    const float4* base = hs + (long long)b * SS * HV + t;
    float4 a0 = make_float4(0.f, 0.f, 0.f, 0.f);
    float4 a1 = a0, a2 = a0, a3 = a0;
    int i = 0;
    for (; i + 4 <= cnt; i += 4) {
        const int q0 = s_list[i], q1 = s_list[i + 1];
        const int q2 = s_list[i + 2], q3 = s_list[i + 3];
        const float4 x0 = __ldg(base + (long long)q0 * HV);
        const float4 x1 = __ldg(base + (long long)q1 * HV);
        const float4 x2 = __ldg(base + (long long)q2 * HV);
        const float4 x3 = __ldg(base + (long long)q3 * HV);
        a0.x += x0.x; a0.y += x0.y; a0.z += x0.z; a0.w += x0.w;
        a1.x += x1.x; a1.y += x1.y; a1.z += x1.z; a1.w += x1.w;
        a2.x += x2.x; a2.y += x2.y; a2.z += x2.z; a2.w += x2.w;
        a3.x += x3.x; a3.y += x3.y; a3.z += x3.z; a3.w += x3.w;
    }
    for (; i < cnt; i++) {
        const float4 x = __ldg(base + (long long)s_list[i] * HV);
        a0.x += x.x; a0.y += x.y; a0.z += x.z; a0.w += x.w;
    }
    float4 r;
    r.x = ((a0.x + a1.x) + (a2.x + a3.x)) * scale;
    r.y = ((a0.y + a1.y) + (a2.y + a3.y)) * scale;
    r.z = ((a0.z + a1.z) + (a2.z + a3.z)) * scale;
    r.w = ((a0.w + a1.w) + (a2.w + a3.w)) * scale;
    out[((long long)b * LL + l) * HV + t] = r;

    if (t == 0 && mask != nullptr)
        mask[(long long)b * LL + l] = (s_total > 0) ? 1.0f : 0.0f;
}

// ---------------------------------------------------------------------------
// Launch
// ---------------------------------------------------------------------------
extern "C" void kernel_launch(void* const* d_in, const int* in_sizes, int n_in,
                              void* d_out, int out_size) {
    const float*         hs  = (const float*)d_in[0];          // [B,S,H] f32
    const int2*          ppi = (const int2*)d_in[1];           // [B,S,2] i32
    const unsigned char* pad = (const unsigned char*)d_in[2];  // [B,S] bool

    const float scale = sqrtf((float)HH) / (float)(KK * KK);

    maxx_kernel<<<BB, 512>>>(ppi);
    kidx_kernel<<<dim3(SS / 512, BB), 256>>>(ppi, pad);

    float* out  = (float*)d_out;
    float* mask = nullptr;
    const long long pooled_elems = (long long)BB * LL * HH;
    if ((long long)out_size >= pooled_elems + (long long)BB * LL)
        mask = out + pooled_elems;

    pool_kernel<<<dim3(LL, BB), HV>>>((const float4*)hs, (float4*)out, mask, scale);
}